// round 3
// baseline (speedup 1.0000x reference)
#include <cuda_runtime.h>

#define BB   8
#define LL   24
#define HPL  32
#define HID  10
#define PIX  4096
#define NCH  768      // N = L*HPL
#define C3   96
#define OC   64

// output section offsets (elements)
#define OFF_LOGITS 0ULL
#define OFF_COEFF  50331648ULL
#define OFF_WA     100663296ULL
#define OFF_WB     125829120ULL
#define OFF_MIXED  150994944ULL

// scratch (no allocations allowed -> device globals)
__device__ float g_xmean[BB][2 * NCH];          // per-(b,channel) mean of x
__device__ float g_psum[2][BB][16][HPL];        // per-tile partial sums of mixed (double buffered by layer parity)

// ---------------- packed f32x2 helpers (Blackwell FFMA2) ----------------
__device__ __forceinline__ unsigned long long pack2(float v) {
    unsigned long long r;
    asm("mov.b64 %0, {%1, %1};" : "=l"(r) : "f"(v));
    return r;
}
__device__ __forceinline__ unsigned long long packf2(float lo, float hi) {
    unsigned long long r;
    asm("mov.b64 %0, {%1, %2};" : "=l"(r) : "f"(lo), "f"(hi));
    return r;
}
__device__ __forceinline__ unsigned long long ffma2(unsigned long long a, unsigned long long b, unsigned long long c) {
    unsigned long long d;
    asm("fma.rn.f32x2 %0, %1, %2, %3;" : "=l"(d) : "l"(a), "l"(b), "l"(c));
    return d;
}
__device__ __forceinline__ float2 unpack2(unsigned long long a) {
    float2 f;
    asm("mov.b64 {%0, %1}, %2;" : "=f"(f.x), "=f"(f.y) : "l"(a));
    return f;
}

// ---------------- channel means of x (all layers, upfront) ----------------
__global__ __launch_bounds__(256) void means_kernel(const float* __restrict__ x) {
    int ch = blockIdx.x;   // b*1536 + c
    const float4* p = reinterpret_cast<const float4*>(x + (size_t)ch * PIX);
    float s = 0.f;
    for (int i = threadIdx.x; i < PIX / 4; i += 256) {
        float4 v = p[i];
        s += (v.x + v.y) + (v.z + v.w);
    }
    #pragma unroll
    for (int o = 16; o; o >>= 1) s += __shfl_xor_sync(~0u, s, o);
    __shared__ float sb[8];
    if ((threadIdx.x & 31) == 0) sb[threadIdx.x >> 5] = s;
    __syncthreads();
    if (threadIdx.x == 0) {
        float t = 0.f;
        #pragma unroll
        for (int w = 0; w < 8; w++) t += sb[w];
        int b = ch / 1536, c = ch % 1536;
        g_xmean[b][c] = t * (1.0f / PIX);
    }
}

// ---------------- one recurrent layer ----------------
__global__ __launch_bounds__(256) void layer_kernel(
    const float* __restrict__ x,
    const float* __restrict__ W1, const float* __restrict__ b1,
    const float* __restrict__ W2, const float* __restrict__ b2,
    const float* __restrict__ Wc, const float* __restrict__ bc,
    float* __restrict__ out, int l)
{
    __shared__ __align__(16) float2 wc_s[C3][HPL];   // (Wc[2op][c], Wc[2op+1][c]) : 24 KB
    __shared__ float gc_s[C3];
    __shared__ float hm_s[HID];
    __shared__ float glc_s[OC];
    __shared__ float red_s[8][HPL];

    const int tid  = threadIdx.x;
    const int b    = blockIdx.y;
    const int tile = blockIdx.x;
    const int p    = tile * 256 + tid;

    // --- stage Wc[l] transposed + output-channel-paired ---
    const float* wcl = Wc + (size_t)l * OC * C3;
    for (int idx = tid; idx < HPL * C3; idx += 256) {
        int op = idx / C3, c = idx % C3;     // coalesced over c
        wc_s[c][op] = make_float2(wcl[(2 * op) * C3 + c], wcl[(2 * op + 1) * C3 + c]);
    }

    // --- gc (channel means of cat) ---
    const int rbuf = (l - 1) & 1;   // buffer written by previous layer
    const int wbuf = l & 1;         // buffer this layer writes
    if (tid < C3) {
        float m;
        if (tid < 32)      m = g_xmean[b][l * HPL + tid];
        else if (tid < 64) m = g_xmean[b][NCH + l * HPL + (tid - 32)];
        else {
            if (l == 0) m = 0.f;
            else {
                float s = 0.f;
                #pragma unroll
                for (int t = 0; t < 16; t++) s += g_psum[rbuf][b][t][tid - 64];
                m = s * (1.0f / PIX);
            }
        }
        gc_s[tid] = m;
    }
    __syncthreads();

    // --- tiny MLP: hmid = silu(gc @ W1^T + b1) ---
    if (tid < HID) {
        const float* w1 = W1 + (size_t)l * HID * C3 + tid * C3;
        float z = b1[l * HID + tid];
        #pragma unroll
        for (int m = 0; m < C3; m++) z += gc_s[m] * w1[m];
        hm_s[tid] = z * __fdividef(1.0f, 1.0f + __expf(-z));
    }
    __syncthreads();

    // --- glc = hmid @ W2^T + b2 + bc (per-output-channel constant) ---
    if (tid < OC) {
        const float* w2 = W2 + (size_t)l * OC * HID + tid * HID;
        float z = b2[l * OC + tid] + bc[l * OC + tid];
        #pragma unroll
        for (int h = 0; h < HID; h++) z += hm_s[h] * w2[h];
        glc_s[tid] = z;
    }
    __syncthreads();

    // --- accumulators: one f32x2 per HPL group (o = 2op, 2op+1), seeded with glc ---
    unsigned long long acc[HPL];
    #pragma unroll
    for (int op = 0; op < HPL; op++)
        acc[op] = packf2(glc_s[2 * op], glc_s[2 * op + 1]);

    const float* xa = x + ((size_t)b * 1536 + l * HPL) * PIX + p;
    const float* xb = xa + (size_t)NCH * PIX;
    const float* pv = out + OFF_MIXED + ((size_t)b * NCH + (l - 1) * HPL) * PIX + p;

    // --- main 96-channel x 64-output GEMM (packed FFMA2) ---
    #pragma unroll
    for (int seg = 0; seg < 3; seg++) {
        if (seg == 2 && l == 0) break;   // prev = 0 contributes nothing exactly
        const float* src = (seg == 0) ? xa : (seg == 1) ? xb : pv;
        #pragma unroll
        for (int g = 0; g < 4; g++) {
            float vbuf[8];
            #pragma unroll
            for (int i = 0; i < 8; i++) vbuf[i] = src[(g * 8 + i) * PIX];
            #pragma unroll
            for (int i = 0; i < 8; i++) {
                unsigned long long vp = pack2(vbuf[i]);
                const ulonglong2* wrow =
                    reinterpret_cast<const ulonglong2*>(&wc_s[seg * 32 + g * 8 + i][0]);
                #pragma unroll
                for (int q = 0; q < 16; q++) {
                    ulonglong2 ww = wrow[q];
                    acc[2 * q]     = ffma2(vp, ww.x, acc[2 * q]);
                    acc[2 * q + 1] = ffma2(vp, ww.y, acc[2 * q + 1]);
                }
            }
        }
    }

    // --- epilogue: logits / coeff / wa / wb / mixed + per-group partial sums ---
    const int lane = tid & 31;
    const int wrp  = tid >> 5;
    const size_t base_bl = ((size_t)b * LL + l) * HPL;
    float mysum = 0.f;

    #pragma unroll
    for (int op = 0; op < HPL; op++) {
        float2 s = unpack2(acc[op]);
        size_t ci = base_bl + op;
        size_t li = ci * 2 * PIX + p;
        out[OFF_LOGITS + li]       = s.x;
        out[OFF_LOGITS + li + PIX] = s.y;

        float d   = s.y - s.x;
        float wbv = __fdividef(1.0f, 1.0f + __expf(-d));
        float wav = 1.0f - wbv;
        out[OFF_COEFF + li]       = wav;
        out[OFF_COEFF + li + PIX] = wbv;

        size_t si = ci * PIX + p;
        out[OFF_WA + si] = wav;
        out[OFF_WB + si] = wbv;

        // mixed = v[3op] + wb*(v[3op+1] - v[3op]); m is compile-time per unrolled iter
        const int m0 = 3 * op, m1 = 3 * op + 1;
        float va = (m0 < 32) ? xa[m0 * PIX]
                 : (m0 < 64) ? xb[(m0 - 32) * PIX]
                             : ((l == 0) ? 0.f : pv[(m0 - 64) * PIX]);
        float vb = (m1 < 32) ? xa[m1 * PIX]
                 : (m1 < 64) ? xb[(m1 - 32) * PIX]
                             : ((l == 0) ? 0.f : pv[(m1 - 64) * PIX]);
        float mix = va + wbv * (vb - va);
        out[OFF_MIXED + si] = mix;

        // warp-reduce mix for this group; lane==op keeps the warp sum
        float r = mix;
        #pragma unroll
        for (int o = 16; o; o >>= 1) r += __shfl_xor_sync(~0u, r, o);
        if (lane == op) mysum = r;
    }

    red_s[wrp][lane] = mysum;
    __syncthreads();
    if (tid < HPL) {
        float t = 0.f;
        #pragma unroll
        for (int w = 0; w < 8; w++) t += red_s[w][tid];
        g_psum[wbuf][b][tile][tid] = t;   // overwrite: no zeroing needed, deterministic
    }
}

// ---------------- launch ----------------
extern "C" void kernel_launch(void* const* d_in, const int* in_sizes, int n_in,
                              void* d_out, int out_size) {
    const float* x  = (const float*)d_in[0];
    const float* W1 = (const float*)d_in[1];
    const float* b1 = (const float*)d_in[2];
    const float* W2 = (const float*)d_in[3];
    const float* b2 = (const float*)d_in[4];
    const float* Wc = (const float*)d_in[5];
    const float* bc = (const float*)d_in[6];
    float* out = (float*)d_out;

    means_kernel<<<BB * 2 * NCH, 256>>>(x);
    for (int l = 0; l < LL; l++)
        layer_kernel<<<dim3(16, BB), 256>>>(x, W1, b1, W2, b2, Wc, bc, out, l);
}

// round 5
// speedup vs baseline: 1.2728x; 1.2728x over previous
#include <cuda_runtime.h>

#define BB    8
#define LL    24
#define HPL   32
#define HID   10
#define PIX   4096
#define NCH   768      // N = L*HPL
#define C3    96
#define OC    64
#define NTILE 32       // pixel tiles of 128
#define NQ    4        // output quarter-groups (16 outputs each)

// output section offsets (elements)
#define OFF_LOGITS 0ULL
#define OFF_COEFF  50331648ULL
#define OFF_WA     100663296ULL
#define OFF_WB     125829120ULL
#define OFF_MIXED  150994944ULL

// scratch (no allocations allowed -> device globals)
__device__ float g_xmean[BB][2 * NCH];               // per-(b,channel) mean of x
__device__ float g_psum[2][BB][NTILE][HPL];          // per-tile partial sums of mixed

// ---------------- packed f32x2 helpers (Blackwell FFMA2) ----------------
__device__ __forceinline__ unsigned long long pack2(float v) {
    unsigned long long r;
    asm("mov.b64 %0, {%1, %1};" : "=l"(r) : "f"(v));
    return r;
}
__device__ __forceinline__ unsigned long long packf2(float lo, float hi) {
    unsigned long long r;
    asm("mov.b64 %0, {%1, %2};" : "=l"(r) : "f"(lo), "f"(hi));
    return r;
}
__device__ __forceinline__ unsigned long long ffma2(unsigned long long a, unsigned long long b, unsigned long long c) {
    unsigned long long d;
    asm("fma.rn.f32x2 %0, %1, %2, %3;" : "=l"(d) : "l"(a), "l"(b), "l"(c));
    return d;
}
__device__ __forceinline__ float2 unpack2(unsigned long long a) {
    float2 f;
    asm("mov.b64 {%0, %1}, %2;" : "=f"(f.x), "=f"(f.y) : "l"(a));
    return f;
}

// ---------------- channel means of x (all layers, upfront) ----------------
__global__ __launch_bounds__(256) void means_kernel(const float* __restrict__ x) {
    int ch = blockIdx.x;   // b*1536 + c
    const float4* p = reinterpret_cast<const float4*>(x + (size_t)ch * PIX);
    float s = 0.f;
    for (int i = threadIdx.x; i < PIX / 4; i += 256) {
        float4 v = p[i];
        s += (v.x + v.y) + (v.z + v.w);
    }
    #pragma unroll
    for (int o = 16; o; o >>= 1) s += __shfl_xor_sync(~0u, s, o);
    __shared__ float sb[8];
    if ((threadIdx.x & 31) == 0) sb[threadIdx.x >> 5] = s;
    __syncthreads();
    if (threadIdx.x == 0) {
        float t = 0.f;
        #pragma unroll
        for (int w = 0; w < 8; w++) t += sb[w];
        int b = ch / 1536, c = ch % 1536;
        g_xmean[b][c] = t * (1.0f / PIX);
    }
}

// ---------------- one recurrent layer (quarter of outputs per block) ------
__global__ __launch_bounds__(128) void layer_kernel(
    const float* __restrict__ x,
    const float* __restrict__ W1, const float* __restrict__ b1,
    const float* __restrict__ W2, const float* __restrict__ b2,
    const float* __restrict__ Wc, const float* __restrict__ bc,
    float* __restrict__ out, int l)
{
    __shared__ __align__(16) float2 wc_s[C3][8];   // (Wc[2op][c], Wc[2op+1][c]) for 8 op-groups : 6 KB
    __shared__ float gc_s[C3];
    __shared__ float hm_s[HID];
    __shared__ float glc_s[16];                    // only this block's 16 outputs
    __shared__ float red_s[4][8];

    const int tid   = threadIdx.x;
    const int b     = blockIdx.y;
    const int tile  = blockIdx.x;
    const int q     = blockIdx.z;                  // output quarter
    const int qbase = q * 8;                       // first op-group (of 8) owned
    const int p     = tile * 128 + tid;

    // --- stage Wc[l] (16 rows) transposed + output-channel-paired ---
    const float* wcl = Wc + (size_t)l * OC * C3;
    for (int idx = tid; idx < 8 * C3; idx += 128) {
        int opl = idx / C3, c = idx % C3;          // coalesced over c
        int op = qbase + opl;
        wc_s[c][opl] = make_float2(wcl[(2 * op) * C3 + c], wcl[(2 * op + 1) * C3 + c]);
    }

    // --- gc (channel means of cat) ---
    const int rbuf = (l - 1) & 1;
    const int wbuf = l & 1;
    if (tid < C3) {
        float m;
        if (tid < 32)      m = g_xmean[b][l * HPL + tid];
        else if (tid < 64) m = g_xmean[b][NCH + l * HPL + (tid - 32)];
        else {
            if (l == 0) m = 0.f;
            else {
                float s = 0.f;
                #pragma unroll
                for (int t = 0; t < NTILE; t++) s += g_psum[rbuf][b][t][tid - 64];
                m = s * (1.0f / PIX);
            }
        }
        gc_s[tid] = m;
    }
    __syncthreads();

    // --- tiny MLP: hmid = silu(gc @ W1^T + b1) ---
    if (tid < HID) {
        const float* w1 = W1 + (size_t)l * HID * C3 + tid * C3;
        float z = b1[l * HID + tid];
        #pragma unroll
        for (int m = 0; m < C3; m++) z += gc_s[m] * w1[m];
        hm_s[tid] = z * __fdividef(1.0f, 1.0f + __expf(-z));
    }
    __syncthreads();

    // --- glc for this block's 16 outputs ---
    if (tid < 16) {
        int o = 2 * qbase + tid;
        const float* w2 = W2 + (size_t)l * OC * HID + o * HID;
        float z = b2[l * OC + o] + bc[l * OC + o];
        #pragma unroll
        for (int h = 0; h < HID; h++) z += hm_s[h] * w2[h];
        glc_s[tid] = z;
    }
    __syncthreads();

    // --- accumulators: 8 f32x2 (16 outputs), seeded with glc ---
    unsigned long long acc[8];
    #pragma unroll
    for (int opl = 0; opl < 8; opl++)
        acc[opl] = packf2(glc_s[2 * opl], glc_s[2 * opl + 1]);

    const float* xa = x + ((size_t)b * 1536 + l * HPL) * PIX + p;
    const float* xb = xa + (size_t)NCH * PIX;
    const float* pv = out + OFF_MIXED + ((size_t)b * NCH + (l - 1) * HPL) * PIX + p;

    // --- main 96-channel x 16-output GEMM (packed FFMA2) ---
    #pragma unroll
    for (int seg = 0; seg < 3; seg++) {
        if (seg == 2 && l == 0) break;   // prev = 0 contributes nothing exactly
        const float* src = (seg == 0) ? xa : (seg == 1) ? xb : pv;
        #pragma unroll
        for (int g = 0; g < 4; g++) {
            float vbuf[8];
            #pragma unroll
            for (int i = 0; i < 8; i++) vbuf[i] = src[(g * 8 + i) * PIX];
            #pragma unroll
            for (int i = 0; i < 8; i++) {
                unsigned long long vp = pack2(vbuf[i]);
                const ulonglong2* wrow =
                    reinterpret_cast<const ulonglong2*>(&wc_s[seg * 32 + g * 8 + i][0]);
                #pragma unroll
                for (int qq = 0; qq < 4; qq++) {
                    ulonglong2 ww = wrow[qq];
                    acc[2 * qq]     = ffma2(vp, ww.x, acc[2 * qq]);
                    acc[2 * qq + 1] = ffma2(vp, ww.y, acc[2 * qq + 1]);
                }
            }
        }
    }

    // --- epilogue: logits / coeff / wa / wb / mixed + per-group partial sums ---
    const int lane = tid & 31;
    const int wrp  = tid >> 5;
    const size_t base_bl = ((size_t)b * LL + l) * HPL;
    float mysum = 0.f;

    #pragma unroll
    for (int opl = 0; opl < 8; opl++) {
        const int op = qbase + opl;
        float2 s = unpack2(acc[opl]);
        size_t ci = base_bl + op;
        size_t li = ci * 2 * PIX + p;
        out[OFF_LOGITS + li]       = s.x;
        out[OFF_LOGITS + li + PIX] = s.y;

        float d   = s.y - s.x;
        float wbv = __fdividef(1.0f, 1.0f + __expf(-d));
        float wav = 1.0f - wbv;
        out[OFF_COEFF + li]       = wav;
        out[OFF_COEFF + li + PIX] = wbv;

        size_t si = ci * PIX + p;
        out[OFF_WA + si] = wav;
        out[OFF_WB + si] = wbv;

        // mixed = v[3op] + wb*(v[3op+1] - v[3op]); indices compile-time per iter
        const int m0 = 3 * op, m1 = 3 * op + 1;
        float va = (m0 < 32) ? xa[m0 * PIX]
                 : (m0 < 64) ? xb[(m0 - 32) * PIX]
                             : ((l == 0) ? 0.f : pv[(m0 - 64) * PIX]);
        float vb = (m1 < 32) ? xa[m1 * PIX]
                 : (m1 < 64) ? xb[(m1 - 32) * PIX]
                             : ((l == 0) ? 0.f : pv[(m1 - 64) * PIX]);
        float mix = va + wbv * (vb - va);
        out[OFF_MIXED + si] = mix;

        // warp-reduce mix for this op; lane==opl keeps the warp sum
        float r = mix;
        #pragma unroll
        for (int o = 16; o; o >>= 1) r += __shfl_xor_sync(~0u, r, o);
        if (lane == opl) mysum = r;
    }

    if (lane < 8) red_s[wrp][lane] = mysum;
    __syncthreads();
    if (tid < 8) {
        float t = red_s[0][tid] + red_s[1][tid] + red_s[2][tid] + red_s[3][tid];
        g_psum[wbuf][b][tile][qbase + tid] = t;   // each op written by exactly one block
    }
}

// ---------------- launch ----------------
extern "C" void kernel_launch(void* const* d_in, const int* in_sizes, int n_in,
                              void* d_out, int out_size) {
    const float* x  = (const float*)d_in[0];
    const float* W1 = (const float*)d_in[1];
    const float* b1 = (const float*)d_in[2];
    const float* W2 = (const float*)d_in[3];
    const float* b2 = (const float*)d_in[4];
    const float* Wc = (const float*)d_in[5];
    const float* bc = (const float*)d_in[6];
    float* out = (float*)d_out;

    means_kernel<<<BB * 2 * NCH, 256>>>(x);
    for (int l = 0; l < LL; l++)
        layer_kernel<<<dim3(NTILE, BB, NQ), 128>>>(x, W1, b1, W2, b2, Wc, bc, out, l);
}